// round 16
// baseline (speedup 1.0000x reference)
#include <cuda_runtime.h>
#include <math.h>
#include <stdint.h>

#define BB     16
#define CC     256
#define HH     64
#define WWID   64
#define PP     4096   // HH*WWID
#define TT     1024   // 32*32 pooled tokens
#define NHEADS 8
#define DHEAD  32
#define NTIL   4096   // 16 b * 256 tiles (16x16 tiles of 4x4 outputs)
#define PSPLIT 18     // p in [0,PSPLIT) -> tensor 3xTF32; [PSPLIT,36) -> fp32 fma

// ---------------- scratch (device globals; no allocs allowed) ----------------
__device__ float         g_pooled[BB*CC*TT];           // [b][c][t]
__device__ unsigned char g_idx   [BB*CC*TT];           // argmax 0..3
__device__ float         g_q   [BB*NHEADS*DHEAD*TT];   // [bh][dhi][t]
__device__ float         g_k   [BB*NHEADS*DHEAD*TT];
__device__ float         g_v   [BB*NHEADS*DHEAD*TT];
__device__ float         g_attn[BB*NHEADS*DHEAD*TT];   // [bh][dhi][t]
__device__ float         g_proj[BB*CC*TT];             // [b][c][t], pre-scaled by tanh(gamma)
__device__ float         g_U[36*CC*CC];                // [p][ic][oc]
__device__ float         g_V[36*CC*NTIL];              // [p][ic][tile]
__device__ float         g_M[36*CC*NTIL];              // [p][oc][tile]

// ---------------- tf32 mma helpers (fragment mapping validated R13/R14) -----
__device__ __forceinline__ float f2tf(float v) {
    uint32_t u;
    asm("cvt.rna.tf32.f32 %0, %1;" : "=r"(u) : "f"(v));
    return __uint_as_float(u);
}
__device__ __forceinline__ void split2(float v, float& hi, float& lo) {
    hi = f2tf(v);
    lo = f2tf(v - hi);
}
__device__ __forceinline__ void mma_tf32(float4& c, const uint32_t* a, uint2 b) {
    asm volatile(
        "mma.sync.aligned.m16n8k8.row.col.f32.tf32.tf32.f32 "
        "{%0,%1,%2,%3}, {%4,%5,%6,%7}, {%8,%9}, {%0,%1,%2,%3};"
        : "+f"(c.x), "+f"(c.y), "+f"(c.z), "+f"(c.w)
        : "r"(a[0]), "r"(a[1]), "r"(a[2]), "r"(a[3]), "r"(b.x), "r"(b.y));
}

// =====================================================================
// Kernel 1: 1x1 conv (feature reduce) + bias + 2x2 maxpool with indices
// =====================================================================
__global__ __launch_bounds__(256) void k_fr_pool(
    const float* __restrict__ x, const float* __restrict__ frw,
    const float* __restrict__ frb)
{
    __shared__ float Xs[32][128];
    __shared__ float Ws[64][32];
    int tid = threadIdx.x;
    int hp = blockIdx.x, ocT = blockIdx.y, b = blockIdx.z;
    int oc0 = ocT * 64;
    int ocg = tid >> 5;
    int pxg = tid & 31;

    float acc[8][4];
#pragma unroll
    for (int i = 0; i < 8; i++)
#pragma unroll
        for (int j = 0; j < 4; j++) acc[i][j] = 0.f;

    const float* xb = x + (size_t)b*CC*PP + hp*128;

    for (int c0 = 0; c0 < CC; c0 += 32) {
#pragma unroll
        for (int j = 0; j < 4; j++) {
            int f = tid + j*256;
            int k = f >> 5, c4 = f & 31;
            *(float4*)&Xs[k][c4*4] = *(const float4*)(xb + (size_t)(c0+k)*PP + c4*4);
        }
#pragma unroll
        for (int j = 0; j < 8; j++) {
            int f = tid + j*256;
            int oc = f >> 5, k = f & 31;
            Ws[oc][k] = frw[(size_t)(oc0+oc)*CC + c0 + k];
        }
        __syncthreads();
#pragma unroll 8
        for (int k = 0; k < 32; k++) {
            float4 xv = *(const float4*)&Xs[k][pxg*4];
#pragma unroll
            for (int i = 0; i < 8; i++) {
                float w = Ws[ocg*8+i][k];
                acc[i][0] = fmaf(w, xv.x, acc[i][0]);
                acc[i][1] = fmaf(w, xv.y, acc[i][1]);
                acc[i][2] = fmaf(w, xv.z, acc[i][2]);
                acc[i][3] = fmaf(w, xv.w, acc[i][3]);
            }
        }
        __syncthreads();
    }

    bool low = (pxg < 16);
#pragma unroll
    for (int i = 0; i < 8; i++) {
        int oc = oc0 + ocg*8 + i;
        float bi = frb[oc];
        float a0 = acc[i][0]+bi, a1 = acc[i][1]+bi;
        float a2 = acc[i][2]+bi, a3 = acc[i][3]+bi;
        float p0 = __shfl_xor_sync(0xffffffffu, a0, 16);
        float p1 = __shfl_xor_sync(0xffffffffu, a1, 16);
        float p2 = __shfl_xor_sync(0xffffffffu, a2, 16);
        float p3 = __shfl_xor_sync(0xffffffffu, a3, 16);
        if (low) {
            size_t base = ((size_t)b*CC + oc)*TT + hp*32 + pxg*2;
            {   float best = a0; int am = 0;
                if (a1 > best) { best = a1; am = 1; }
                if (p0 > best) { best = p0; am = 2; }
                if (p1 > best) { best = p1; am = 3; }
                g_pooled[base] = best; g_idx[base] = (unsigned char)am; }
            {   float best = a2; int am = 0;
                if (a3 > best) { best = a3; am = 1; }
                if (p2 > best) { best = p2; am = 2; }
                if (p3 > best) { best = p3; am = 3; }
                g_pooled[base+1] = best; g_idx[base+1] = (unsigned char)am; }
        }
    }
}

// =====================================================================
// Kernel 2: QKV projection via mma.sync tf32 (unchanged from R14)
// =====================================================================
__global__ __launch_bounds__(256, 2) void k_qkv_mma(
    const float* __restrict__ wq, const float* __restrict__ wk,
    const float* __restrict__ wv)
{
    __shared__ float As[2][2][64][8];
    __shared__ float Bs[2][16][136];
    int tid = threadIdx.x;
    int lane = tid & 31, w = tid >> 5;
    int r = lane >> 2, cq = lane & 3;
    int wm = w >> 2, wn = w & 3;
    int t0 = blockIdx.x * 128;
    int mat = blockIdx.y >> 2, dT = blockIdx.y & 3;
    int b = blockIdx.z;
    int m0 = dT * 64;

    const float* W  = (mat == 0) ? wq : (mat == 1) ? wk : wv;
    const float* Bg = g_pooled + (size_t)b*CC*TT;

    int a_kk = tid >> 4, a_m = (tid & 15) * 4;
    int a_col = ((a_kk & 3) << 1) | ((a_kk >> 2) & 1);
    int a_ks  = a_kk >> 3;
    int b_kk0 = tid >> 5,        b_tq0 = (tid & 31) * 4;
    int b_kk1 = (tid >> 5) + 8,  b_tq1 = b_tq0;

    float4 acc[2][4];
#pragma unroll
    for (int mt = 0; mt < 2; mt++)
#pragma unroll
        for (int nt = 0; nt < 4; nt++) acc[mt][nt] = make_float4(0.f,0.f,0.f,0.f);

    float4 ra, rb0, rb1;
    ra  = *(const float4*)(W  + (size_t)a_kk*CC + m0 + a_m);
    rb0 = *(const float4*)(Bg + (size_t)b_kk0*TT + t0 + b_tq0);
    rb1 = *(const float4*)(Bg + (size_t)b_kk1*TT + t0 + b_tq1);
    As[0][a_ks][a_m+0][a_col] = f2tf(ra.x);
    As[0][a_ks][a_m+1][a_col] = f2tf(ra.y);
    As[0][a_ks][a_m+2][a_col] = f2tf(ra.z);
    As[0][a_ks][a_m+3][a_col] = f2tf(ra.w);
    *(float4*)&Bs[0][b_kk0][b_tq0] = make_float4(f2tf(rb0.x), f2tf(rb0.y), f2tf(rb0.z), f2tf(rb0.w));
    *(float4*)&Bs[0][b_kk1][b_tq1] = make_float4(f2tf(rb1.x), f2tf(rb1.y), f2tf(rb1.z), f2tf(rb1.w));
    __syncthreads();
    ra  = *(const float4*)(W  + (size_t)(16 + a_kk)*CC + m0 + a_m);
    rb0 = *(const float4*)(Bg + (size_t)(16 + b_kk0)*TT + t0 + b_tq0);
    rb1 = *(const float4*)(Bg + (size_t)(16 + b_kk1)*TT + t0 + b_tq1);

    for (int s = 0; s < 16; s++) {
        int cur = s & 1;
#pragma unroll
        for (int ks = 0; ks < 2; ks++) {
            uint32_t a[2][4];
#pragma unroll
            for (int mt = 0; mt < 2; mt++) {
                int mb = wm*32 + mt*16;
                float2 lo = *(const float2*)&As[cur][ks][mb + r][cq*2];
                float2 hi = *(const float2*)&As[cur][ks][mb + r + 8][cq*2];
                a[mt][0] = __float_as_uint(lo.x); a[mt][1] = __float_as_uint(hi.x);
                a[mt][2] = __float_as_uint(lo.y); a[mt][3] = __float_as_uint(hi.y);
            }
#pragma unroll
            for (int nt = 0; nt < 4; nt++) {
                int nb = wn*32 + nt*8 + r;
                uint2 bf;
                bf.x = __float_as_uint(Bs[cur][ks*8 + cq][nb]);
                bf.y = __float_as_uint(Bs[cur][ks*8 + cq + 4][nb]);
                mma_tf32(acc[0][nt], a[0], bf);
                mma_tf32(acc[1][nt], a[1], bf);
            }
        }
        if (s < 15) {
            __syncthreads();
            int nxt = cur ^ 1;
            As[nxt][a_ks][a_m+0][a_col] = f2tf(ra.x);
            As[nxt][a_ks][a_m+1][a_col] = f2tf(ra.y);
            As[nxt][a_ks][a_m+2][a_col] = f2tf(ra.z);
            As[nxt][a_ks][a_m+3][a_col] = f2tf(ra.w);
            *(float4*)&Bs[nxt][b_kk0][b_tq0] = make_float4(f2tf(rb0.x), f2tf(rb0.y), f2tf(rb0.z), f2tf(rb0.w));
            *(float4*)&Bs[nxt][b_kk1][b_tq1] = make_float4(f2tf(rb1.x), f2tf(rb1.y), f2tf(rb1.z), f2tf(rb1.w));
            if (s < 14) {
                int k0 = (s + 2) * 16;
                ra  = *(const float4*)(W  + (size_t)(k0 + a_kk)*CC + m0 + a_m);
                rb0 = *(const float4*)(Bg + (size_t)(k0 + b_kk0)*TT + t0 + b_tq0);
                rb1 = *(const float4*)(Bg + (size_t)(k0 + b_kk1)*TT + t0 + b_tq1);
            }
            __syncthreads();
        }
    }

    float* O = (mat == 0) ? g_q : (mat == 1) ? g_k : g_v;
#pragma unroll
    for (int mt = 0; mt < 2; mt++) {
        int dbase = m0 + wm*32 + mt*16;
#pragma unroll
        for (int nt = 0; nt < 4; nt++) {
            float4 c = acc[mt][nt];
            int t  = t0 + wn*32 + nt*8 + cq*2;
            int d1 = dbase + r, d2 = dbase + r + 8;
            size_t a1 = (((size_t)b*NHEADS + (d1 & 7))*DHEAD + (d1 >> 3))*TT + t;
            size_t a2 = (((size_t)b*NHEADS + (d2 & 7))*DHEAD + (d2 >> 3))*TT + t;
            *(float2*)&O[a1] = make_float2(c.x, c.y);
            *(float2*)&O[a2] = make_float2(c.z, c.w);
        }
    }
}

// =====================================================================
// Kernel 3: flash attention via mma.sync tf32 (unchanged from R14)
// =====================================================================
__global__ __launch_bounds__(128) void k_attn_mma()
{
    __shared__ float Qs[128][36];
    __shared__ float Ks[32][40];
    __shared__ float Vs[32][40];
    __shared__ float Ps[4][32][36];

    int tid = threadIdx.x;
    int lane = tid & 31, w = tid >> 5;
    int r = lane >> 2, cq = lane & 3;
    int q0 = blockIdx.x * 128;
    int bh = blockIdx.y;
    const float* Qg = g_q + (size_t)bh*DHEAD*TT;
    const float* Kg = g_k + (size_t)bh*DHEAD*TT;
    const float* Vg = g_v + (size_t)bh*DHEAD*TT;
    const float qscale = 0.17677669529663687f;

#pragma unroll
    for (int j = 0; j < 8; j++) {
        int e = tid + j*128;
        int d = e >> 5, q4 = (e & 31) * 4;
        float4 v = *(const float4*)(Qg + (size_t)d*TT + q0 + q4);
        Qs[q4+0][d] = f2tf(v.x * qscale);
        Qs[q4+1][d] = f2tf(v.y * qscale);
        Qs[q4+2][d] = f2tf(v.z * qscale);
        Qs[q4+3][d] = f2tf(v.w * qscale);
    }

    float mrow[2][2], lrow[2][2];
#pragma unroll
    for (int mt = 0; mt < 2; mt++) {
        mrow[mt][0] = -3.0e38f; mrow[mt][1] = -3.0e38f;
        lrow[mt][0] = 0.f;      lrow[mt][1] = 0.f;
    }
    float4 of[2][4];
#pragma unroll
    for (int mt = 0; mt < 2; mt++)
#pragma unroll
        for (int nt = 0; nt < 4; nt++) of[mt][nt] = make_float4(0.f,0.f,0.f,0.f);

    for (int k0 = 0; k0 < TT; k0 += 32) {
#pragma unroll
        for (int j = 0; j < 2; j++) {
            int e = tid + j*128;
            int d = e >> 3, c4 = (e & 7) * 4;
            float4 kv = *(const float4*)(Kg + (size_t)d*TT + k0 + c4);
            Ks[d][c4+0] = f2tf(kv.x); Ks[d][c4+1] = f2tf(kv.y);
            Ks[d][c4+2] = f2tf(kv.z); Ks[d][c4+3] = f2tf(kv.w);
            float4 vv = *(const float4*)(Vg + (size_t)d*TT + k0 + c4);
            Vs[c4+0][d] = f2tf(vv.x); Vs[c4+1][d] = f2tf(vv.y);
            Vs[c4+2][d] = f2tf(vv.z); Vs[c4+3][d] = f2tf(vv.w);
        }
        __syncthreads();

        float4 s[2][4];
#pragma unroll
        for (int mt = 0; mt < 2; mt++)
#pragma unroll
            for (int nt = 0; nt < 4; nt++) s[mt][nt] = make_float4(0.f,0.f,0.f,0.f);
#pragma unroll
        for (int ks = 0; ks < 4; ks++) {
            uint32_t a[2][4];
#pragma unroll
            for (int mt = 0; mt < 2; mt++) {
                int mb = w*32 + mt*16;
                a[mt][0] = __float_as_uint(Qs[mb + r    ][ks*8 + cq]);
                a[mt][1] = __float_as_uint(Qs[mb + r + 8][ks*8 + cq]);
                a[mt][2] = __float_as_uint(Qs[mb + r    ][ks*8 + cq + 4]);
                a[mt][3] = __float_as_uint(Qs[mb + r + 8][ks*8 + cq + 4]);
            }
#pragma unroll
            for (int nt = 0; nt < 4; nt++) {
                uint2 bf;
                bf.x = __float_as_uint(Ks[ks*8 + cq    ][nt*8 + r]);
                bf.y = __float_as_uint(Ks[ks*8 + cq + 4][nt*8 + r]);
                mma_tf32(s[0][nt], a[0], bf);
                mma_tf32(s[1][nt], a[1], bf);
            }
        }

#pragma unroll
        for (int mt = 0; mt < 2; mt++) {
            float vm0 = -3.0e38f, vm1 = -3.0e38f;
#pragma unroll
            for (int nt = 0; nt < 4; nt++) {
                vm0 = fmaxf(vm0, fmaxf(s[mt][nt].x, s[mt][nt].y));
                vm1 = fmaxf(vm1, fmaxf(s[mt][nt].z, s[mt][nt].w));
            }
            vm0 = fmaxf(vm0, __shfl_xor_sync(0xffffffffu, vm0, 1));
            vm0 = fmaxf(vm0, __shfl_xor_sync(0xffffffffu, vm0, 2));
            vm1 = fmaxf(vm1, __shfl_xor_sync(0xffffffffu, vm1, 1));
            vm1 = fmaxf(vm1, __shfl_xor_sync(0xffffffffu, vm1, 2));
            float mn0 = fmaxf(mrow[mt][0], vm0);
            float mn1 = fmaxf(mrow[mt][1], vm1);
            float al0 = __expf(mrow[mt][0] - mn0);
            float al1 = __expf(mrow[mt][1] - mn1);
            float sum0 = 0.f, sum1 = 0.f;
            int rowa = mt*16 + r, rowb = rowa + 8;
#pragma unroll
            for (int nt = 0; nt < 4; nt++) {
                float p00 = __expf(s[mt][nt].x - mn0);
                float p01 = __expf(s[mt][nt].y - mn0);
                float p10 = __expf(s[mt][nt].z - mn1);
                float p11 = __expf(s[mt][nt].w - mn1);
                Ps[w][rowa][nt*8 + cq*2]     = f2tf(p00);
                Ps[w][rowa][nt*8 + cq*2 + 1] = f2tf(p01);
                Ps[w][rowb][nt*8 + cq*2]     = f2tf(p10);
                Ps[w][rowb][nt*8 + cq*2 + 1] = f2tf(p11);
                sum0 += p00 + p01;
                sum1 += p10 + p11;
            }
            sum0 += __shfl_xor_sync(0xffffffffu, sum0, 1);
            sum0 += __shfl_xor_sync(0xffffffffu, sum0, 2);
            sum1 += __shfl_xor_sync(0xffffffffu, sum1, 1);
            sum1 += __shfl_xor_sync(0xffffffffu, sum1, 2);
            lrow[mt][0] = lrow[mt][0]*al0 + sum0;  mrow[mt][0] = mn0;
            lrow[mt][1] = lrow[mt][1]*al1 + sum1;  mrow[mt][1] = mn1;
#pragma unroll
            for (int nt = 0; nt < 4; nt++) {
                of[mt][nt].x *= al0; of[mt][nt].y *= al0;
                of[mt][nt].z *= al1; of[mt][nt].w *= al1;
            }
        }
        __syncwarp();

#pragma unroll
        for (int ks = 0; ks < 4; ks++) {
            uint32_t a[2][4];
#pragma unroll
            for (int mt = 0; mt < 2; mt++) {
                int mb = mt*16;
                a[mt][0] = __float_as_uint(Ps[w][mb + r    ][ks*8 + cq]);
                a[mt][1] = __float_as_uint(Ps[w][mb + r + 8][ks*8 + cq]);
                a[mt][2] = __float_as_uint(Ps[w][mb + r    ][ks*8 + cq + 4]);
                a[mt][3] = __float_as_uint(Ps[w][mb + r + 8][ks*8 + cq + 4]);
            }
#pragma unroll
            for (int nt = 0; nt < 4; nt++) {
                uint2 bf;
                bf.x = __float_as_uint(Vs[ks*8 + cq    ][nt*8 + r]);
                bf.y = __float_as_uint(Vs[ks*8 + cq + 4][nt*8 + r]);
                mma_tf32(of[0][nt], a[0], bf);
                mma_tf32(of[1][nt], a[1], bf);
            }
        }
        __syncthreads();
    }

    float* Og = g_attn + (size_t)bh*DHEAD*TT;
#pragma unroll
    for (int mt = 0; mt < 2; mt++) {
        float li0 = 1.f / lrow[mt][0];
        float li1 = 1.f / lrow[mt][1];
        int qr = q0 + w*32 + mt*16 + r;
#pragma unroll
        for (int nt = 0; nt < 4; nt++) {
            float4 c = of[mt][nt];
            int d0 = nt*8 + cq*2;
            Og[(size_t)d0*TT + qr]           = c.x * li0;
            Og[(size_t)(d0+1)*TT + qr]       = c.y * li0;
            Og[(size_t)d0*TT + qr + 8]       = c.z * li1;
            Og[(size_t)(d0+1)*TT + qr + 8]   = c.w * li1;
        }
    }
}

// =====================================================================
// Kernel 4: output projection via mma.sync tf32 (unchanged from R14)
// =====================================================================
__global__ __launch_bounds__(256, 2) void k_proj_mma(
    const float* __restrict__ wo, const float* __restrict__ gamma)
{
    __shared__ float As[2][2][64][8];
    __shared__ float Bs[2][16][136];
    int tid = threadIdx.x;
    int lane = tid & 31, w = tid >> 5;
    int r = lane >> 2, cq = lane & 3;
    int wm = w >> 2, wn = w & 3;
    int t0 = blockIdx.x * 128;
    int dT = blockIdx.y;
    int b = blockIdx.z;
    int m0 = dT * 64;

    int a_kk = tid >> 4, a_m = (tid & 15) * 4;
    int a_col = ((a_kk & 3) << 1) | ((a_kk >> 2) & 1);
    int a_ks  = a_kk >> 3;
    int b_kk0 = tid >> 5,       b_tq0 = (tid & 31) * 4;
    int b_kk1 = (tid >> 5) + 8, b_tq1 = b_tq0;

    #define ATTN_ROW(c) (g_attn + (((size_t)b*NHEADS + ((c) & 7))*DHEAD + ((c) >> 3))*TT)

    float4 acc[2][4];
#pragma unroll
    for (int mt = 0; mt < 2; mt++)
#pragma unroll
        for (int nt = 0; nt < 4; nt++) acc[mt][nt] = make_float4(0.f,0.f,0.f,0.f);

    float4 ra, rb0, rb1;
    ra  = *(const float4*)(wo + (size_t)a_kk*CC + m0 + a_m);
    rb0 = *(const float4*)(ATTN_ROW(b_kk0) + t0 + b_tq0);
    rb1 = *(const float4*)(ATTN_ROW(b_kk1) + t0 + b_tq1);
    As[0][a_ks][a_m+0][a_col] = f2tf(ra.x);
    As[0][a_ks][a_m+1][a_col] = f2tf(ra.y);
    As[0][a_ks][a_m+2][a_col] = f2tf(ra.z);
    As[0][a_ks][a_m+3][a_col] = f2tf(ra.w);
    *(float4*)&Bs[0][b_kk0][b_tq0] = make_float4(f2tf(rb0.x), f2tf(rb0.y), f2tf(rb0.z), f2tf(rb0.w));
    *(float4*)&Bs[0][b_kk1][b_tq1] = make_float4(f2tf(rb1.x), f2tf(rb1.y), f2tf(rb1.z), f2tf(rb1.w));
    __syncthreads();
    ra  = *(const float4*)(wo + (size_t)(16 + a_kk)*CC + m0 + a_m);
    rb0 = *(const float4*)(ATTN_ROW(16 + b_kk0) + t0 + b_tq0);
    rb1 = *(const float4*)(ATTN_ROW(16 + b_kk1) + t0 + b_tq1);

    for (int s = 0; s < 16; s++) {
        int cur = s & 1;
#pragma unroll
        for (int ks = 0; ks < 2; ks++) {
            uint32_t a[2][4];
#pragma unroll
            for (int mt = 0; mt < 2; mt++) {
                int mb = wm*32 + mt*16;
                float2 lo = *(const float2*)&As[cur][ks][mb + r][cq*2];
                float2 hi = *(const float2*)&As[cur][ks][mb + r + 8][cq*2];
                a[mt][0] = __float_as_uint(lo.x); a[mt][1] = __float_as_uint(hi.x);
                a[mt][2] = __float_as_uint(lo.y); a[mt][3] = __float_as_uint(hi.y);
            }
#pragma unroll
            for (int nt = 0; nt < 4; nt++) {
                int nb = wn*32 + nt*8 + r;
                uint2 bf;
                bf.x = __float_as_uint(Bs[cur][ks*8 + cq][nb]);
                bf.y = __float_as_uint(Bs[cur][ks*8 + cq + 4][nb]);
                mma_tf32(acc[0][nt], a[0], bf);
                mma_tf32(acc[1][nt], a[1], bf);
            }
        }
        if (s < 15) {
            __syncthreads();
            int nxt = cur ^ 1;
            As[nxt][a_ks][a_m+0][a_col] = f2tf(ra.x);
            As[nxt][a_ks][a_m+1][a_col] = f2tf(ra.y);
            As[nxt][a_ks][a_m+2][a_col] = f2tf(ra.z);
            As[nxt][a_ks][a_m+3][a_col] = f2tf(ra.w);
            *(float4*)&Bs[nxt][b_kk0][b_tq0] = make_float4(f2tf(rb0.x), f2tf(rb0.y), f2tf(rb0.z), f2tf(rb0.w));
            *(float4*)&Bs[nxt][b_kk1][b_tq1] = make_float4(f2tf(rb1.x), f2tf(rb1.y), f2tf(rb1.z), f2tf(rb1.w));
            if (s < 14) {
                int k0 = (s + 2) * 16;
                ra  = *(const float4*)(wo + (size_t)(k0 + a_kk)*CC + m0 + a_m);
                rb0 = *(const float4*)(ATTN_ROW(k0 + b_kk0) + t0 + b_tq0);
                rb1 = *(const float4*)(ATTN_ROW(k0 + b_kk1) + t0 + b_tq1);
            }
            __syncthreads();
        }
    }
    #undef ATTN_ROW

    float tg = tanhf(gamma[0]);
#pragma unroll
    for (int mt = 0; mt < 2; mt++) {
        int dbase = m0 + wm*32 + mt*16;
#pragma unroll
        for (int nt = 0; nt < 4; nt++) {
            float4 c = acc[mt][nt];
            int t  = t0 + wn*32 + nt*8 + cq*2;
            size_t a1 = ((size_t)b*CC + dbase + r)*TT + t;
            size_t a2 = ((size_t)b*CC + dbase + r + 8)*TT + t;
            *(float2*)&g_proj[a1] = make_float2(c.x*tg, c.y*tg);
            *(float2*)&g_proj[a2] = make_float2(c.z*tg, c.w*tg);
        }
    }
}

// =====================================================================
// Winograd F(4x4, 3x3)
// =====================================================================
__device__ __forceinline__ void gfilt(const float a, const float b, const float c,
                                      float* o) {
    o[0] = 0.25f*a;
    o[1] = (-a - b - c) * (1.f/6.f);
    o[2] = (-a + b - c) * (1.f/6.f);
    o[3] = a*(1.f/24.f) + b*(1.f/12.f) + c*(1.f/6.f);
    o[4] = a*(1.f/24.f) - b*(1.f/12.f) + c*(1.f/6.f);
    o[5] = c;
}

__global__ __launch_bounds__(256) void k_wg_wt(const float* __restrict__ cw)
{
    int idx = blockIdx.x*256 + threadIdx.x;
    int oc = idx & 255, ic = idx >> 8;
    const float* g = cw + (size_t)oc*2304 + ic*9;
    float g00=g[0],g01=g[1],g02=g[2],g10=g[3],g11=g[4],g12=g[5],g20=g[6],g21=g[7],g22=g[8];

    float t[6][3];
    {
        float o0[6], o1[6], o2[6];
        gfilt(g00, g10, g20, o0);
        gfilt(g01, g11, g21, o1);
        gfilt(g02, g12, g22, o2);
#pragma unroll
        for (int r = 0; r < 6; r++) { t[r][0]=o0[r]; t[r][1]=o1[r]; t[r][2]=o2[r]; }
    }
#pragma unroll
    for (int r = 0; r < 6; r++) {
        float o[6];
        gfilt(t[r][0], t[r][1], t[r][2], o);
#pragma unroll
        for (int c = 0; c < 6; c++)
            g_U[(size_t)(r*6+c)*CC*CC + (size_t)ic*CC + oc] = o[c];
    }
}

__device__ __forceinline__ void btrans(const float* d, float* o) {
    o[0] = 4.f*d[0] - 5.f*d[2] + d[4];
    o[1] = -4.f*d[1] - 4.f*d[2] + d[3] + d[4];
    o[2] =  4.f*d[1] - 4.f*d[2] - d[3] + d[4];
    o[3] = -2.f*d[1] -     d[2] + 2.f*d[3] + d[4];
    o[4] =  2.f*d[1] -     d[2] - 2.f*d[3] + d[4];
    o[5] =  4.f*d[1] - 5.f*d[3] + d[5];
}

__global__ __launch_bounds__(256) void k_wg_in(const float* __restrict__ x)
{
    int tid = threadIdx.x;
    int tx = tid & 15, ic_l = tid >> 4;
    int ty = blockIdx.x, icT = blockIdx.y, b = blockIdx.z;
    int ic = icT*16 + ic_l;
    int tile = b*256 + ty*16 + tx;

    const float* xp = x + ((size_t)b*CC + ic)*PP;
    int gy0 = ty*4 - 1, gx0 = tx*4 - 1;

    float d[6][6];
#pragma unroll
    for (int i = 0; i < 6; i++) {
        int gy = gy0 + i;
        bool yok = (unsigned)gy < 64u;
#pragma unroll
        for (int j = 0; j < 6; j++) {
            int gx = gx0 + j;
            d[i][j] = (yok && (unsigned)gx < 64u) ? xp[gy*64 + gx] : 0.f;
        }
    }
    float wcol[6][6];
#pragma unroll
    for (int j = 0; j < 6; j++) {
        float col[6] = {d[0][j], d[1][j], d[2][j], d[3][j], d[4][j], d[5][j]};
        float o[6];
        btrans(col, o);
#pragma unroll
        for (int r = 0; r < 6; r++) wcol[r][j] = o[r];
    }
#pragma unroll
    for (int r = 0; r < 6; r++) {
        float o[6];
        btrans(wcol[r], o);
#pragma unroll
        for (int c = 0; c < 6; c++)
            g_V[(size_t)(r*6+c)*CC*NTIL + (size_t)ic*NTIL + tile] = o[c];
    }
}

// ---- W3a: fp32 scalar GEMM for p in [PSPLIT, 36)  (fma pipe)
__global__ __launch_bounds__(256) void k_wg_gemm()
{
    __shared__ float As[32][64];
    __shared__ float Bs[32][64];
    int tid = threadIdx.x;
    int t0 = blockIdx.x*64, oc0 = blockIdx.y*64, p = blockIdx.z + PSPLIT;
    int ng = tid & 15, mg = tid >> 4;

    const float* Vp = g_V + (size_t)p*CC*NTIL;
    const float* Up = g_U + (size_t)p*CC*CC;

    float acc[4][4];
#pragma unroll
    for (int i = 0; i < 4; i++)
#pragma unroll
        for (int j = 0; j < 4; j++) acc[i][j] = 0.f;

    for (int c0 = 0; c0 < CC; c0 += 32) {
#pragma unroll
        for (int j = 0; j < 2; j++) {
            int f = tid + j*256;
            int k = f >> 4, m4 = f & 15;
            *(float4*)&As[k][m4*4] = *(const float4*)(Vp + (size_t)(c0+k)*NTIL + t0 + m4*4);
            *(float4*)&Bs[k][m4*4] = *(const float4*)(Up + (size_t)(c0+k)*CC + oc0 + m4*4);
        }
        __syncthreads();
#pragma unroll 8
        for (int k = 0; k < 32; k++) {
            float4 a  = *(const float4*)&As[k][mg*4];
            float4 bv = *(const float4*)&Bs[k][ng*4];
            float am[4] = {a.x,a.y,a.z,a.w};
            float bn[4] = {bv.x,bv.y,bv.z,bv.w};
#pragma unroll
            for (int mm = 0; mm < 4; mm++)
#pragma unroll
                for (int nn = 0; nn < 4; nn++)
                    acc[mm][nn] = fmaf(am[mm], bn[nn], acc[mm][nn]);
        }
        __syncthreads();
    }

    float* Mp = g_M + (size_t)p*CC*NTIL;
#pragma unroll
    for (int nn = 0; nn < 4; nn++) {
        int oc = oc0 + ng*4 + nn;
        *(float4*)(Mp + (size_t)oc*NTIL + t0 + mg*4) =
            make_float4(acc[0][nn], acc[1][nn], acc[2][nn], acc[3][nn]);
    }
}

// ---- W3b: 3xTF32 tensor GEMM for p in [0, PSPLIT)  (tensor pipe)
// Dynamic smem (51200 B > 48KB static limit): Ah/Al 8192 B each,
// Bh/Bl 17408 B each. 2 CTAs/SM (2*51200 = 102400 B << 227KB).
#define AH(st,ks,m,c) sA_h[(((st)*2 + (ks))*64 + (m))*8 + (c)]
#define AL(st,ks,m,c) sA_l[(((st)*2 + (ks))*64 + (m))*8 + (c)]
#define BH(st,k,n)    sB_h[((st)*16 + (k))*136 + (n)]
#define BL(st,k,n)    sB_l[((st)*16 + (k))*136 + (n)]

__global__ __launch_bounds__(256) void k_wg_gemm_tc()
{
    extern __shared__ float dsm[];
    float* sA_h = dsm;              // 2048 floats
    float* sA_l = dsm + 2048;       // 2048
    float* sB_h = dsm + 4096;       // 4352
    float* sB_l = dsm + 8448;       // 4352  -> total 12800 floats = 51200 B

    int tid = threadIdx.x;
    int lane = tid & 31, w = tid >> 5;
    int r = lane >> 2, cq = lane & 3;
    int wm = w >> 2, wn = w & 3;
    int t0 = blockIdx.x * 128;
    int oc0 = blockIdx.y * 64;
    int p = blockIdx.z;

    const float* Up = g_U + (size_t)p*CC*CC;
    const float* Vp = g_V + (size_t)p*CC*NTIL;

    int a_kk = tid >> 4, a_m = (tid & 15) * 4;
    int a_col = ((a_kk & 3) << 1) | ((a_kk >> 2) & 1);
    int a_ks  = a_kk >> 3;
    int b_kk0 = tid >> 5,       b_tq0 = (tid & 31) * 4;
    int b_kk1 = (tid >> 5) + 8, b_tq1 = b_tq0;

    float4 acc[2][4];
#pragma unroll
    for (int mt = 0; mt < 2; mt++)
#pragma unroll
        for (int nt = 0; nt < 4; nt++) acc[mt][nt] = make_float4(0.f,0.f,0.f,0.f);

    float4 ra, rb0, rb1;

    #define STAGE_TC(st) do {                                                  \
        float h, l;                                                            \
        split2(ra.x, h, l); AH(st,a_ks,a_m+0,a_col) = h; AL(st,a_ks,a_m+0,a_col) = l; \
        split2(ra.y, h, l); AH(st,a_ks,a_m+1,a_col) = h; AL(st,a_ks,a_m+1,a_col) = l; \
        split2(ra.z, h, l); AH(st,a_ks,a_m+2,a_col) = h; AL(st,a_ks,a_m+2,a_col) = l; \
        split2(ra.w, h, l); AH(st,a_ks,a_m+3,a_col) = h; AL(st,a_ks,a_m+3,a_col) = l; \
        float4 hv, lv;                                                         \
        split2(rb0.x, hv.x, lv.x); split2(rb0.y, hv.y, lv.y);                  \
        split2(rb0.z, hv.z, lv.z); split2(rb0.w, hv.w, lv.w);                  \
        *(float4*)&BH(st,b_kk0,b_tq0) = hv; *(float4*)&BL(st,b_kk0,b_tq0) = lv; \
        split2(rb1.x, hv.x, lv.x); split2(rb1.y, hv.y, lv.y);                  \
        split2(rb1.z, hv.z, lv.z); split2(rb1.w, hv.w, lv.w);                  \
        *(float4*)&BH(st,b_kk1,b_tq1) = hv; *(float4*)&BL(st,b_kk1,b_tq1) = lv; \
    } while (0)

    ra  = *(const float4*)(Up + (size_t)a_kk*CC + oc0 + a_m);
    rb0 = *(const float4*)(Vp + (size_t)b_kk0*NTIL + t0 + b_tq0);
    rb1 = *(const float4*)(Vp + (size_t)b_kk1*NTIL + t0 + b_tq1);
    STAGE_TC(0);
    __syncthreads();
    ra  = *(const float4*)(Up + (size_t)(16 + a_kk)*CC + oc0 + a_m);
    rb0 = *(const float4*)(Vp + (size_t)(16 + b_kk0)*NTIL + t0 + b_tq0);
    rb1 = *(const float4*)(Vp + (size_t)(16 + b_kk1)*NTIL + t0 + b_tq1);

    for (int s = 0; s < 16; s++) {
        int cur = s & 1;
#pragma unroll
        for (int ks = 0; ks < 2; ks++) {
            uint32_t ah[2][4], al[2][4];
#pragma unroll
            for (int mt = 0; mt < 2; mt++) {
                int mb = wm*32 + mt*16;
                float2 h0 = *(const float2*)&AH(cur,ks,mb + r,cq*2);
                float2 h1 = *(const float2*)&AH(cur,ks,mb + r + 8,cq*2);
                ah[mt][0] = __float_as_uint(h0.x); ah[mt][1] = __float_as_uint(h1.x);
                ah[mt][2] = __float_as_uint(h0.y); ah[mt][3] = __float_as_uint(h1.y);
                float2 l0 = *(const float2*)&AL(cur,ks,mb + r,cq*2);
                float2 l1 = *(const float2*)&AL(cur,ks,mb + r + 8,cq*2);
                al[mt][0] = __float_as_uint(l0.x); al[mt][1] = __float_as_uint(l1.x);
                al[mt][2] = __float_as_uint(l0.y); al[mt][3] = __float_as_uint(l1.y);
            }
#pragma unroll
            for (int nt = 0; nt < 4; nt++) {
                int nb = wn*32 + nt*8 + r;
                uint2 bh, bl;
                bh.x = __float_as_uint(BH(cur,ks*8 + cq,nb));
                bh.y = __float_as_uint(BH(cur,ks*8 + cq + 4,nb));
                bl.x = __float_as_uint(BL(cur,ks*8 + cq,nb));
                bl.y = __float_as_uint(BL(cur,ks*8 + cq + 4,nb));
#pragma unroll
                for (int mt = 0; mt < 2; mt++) {
                    mma_tf32(acc[mt][nt], ah[mt], bh);   // hi*hi
                    mma_tf32(acc[mt][nt], ah[mt], bl);   // hi*lo
                    mma_tf32(acc[mt][nt], al[mt], bh);   // lo*hi
                }
            }
        }
        if (s < 15) {
            __syncthreads();
            int nxt = cur ^ 1;
            STAGE_TC(nxt);
            if (s < 14) {
                int k0 = (s + 2) * 16;
                ra  = *(const float4*)(Up + (size_t)(k0 + a_kk)*CC + oc0 + a_m);
                rb0 = *(const float4*)(Vp + (size_t)(k0 + b_kk0)*NTIL + t0 + b_tq0);
                rb1 = *(const float4*)(Vp + (size_t)(k0 + b_kk1)*NTIL + t0 + b_tq1);
            }
            __syncthreads();
        }
    }
    #undef STAGE_TC

    float* Mp = g_M + (size_t)p*CC*NTIL;
#pragma unroll
    for (int mt = 0; mt < 2; mt++) {
        int obase = oc0 + wm*32 + mt*16;
#pragma unroll
        for (int nt = 0; nt < 4; nt++) {
            float4 c = acc[mt][nt];
            int t  = t0 + wn*32 + nt*8 + cq*2;
            *(float2*)(Mp + (size_t)(obase + r)*NTIL + t)     = make_float2(c.x, c.y);
            *(float2*)(Mp + (size_t)(obase + r + 8)*NTIL + t) = make_float2(c.z, c.w);
        }
    }
}

__device__ __forceinline__ void atrans(const float* w, float* o) {
    o[0] = w[0] + w[1] + w[2] + w[3] + w[4];
    o[1] = w[1] - w[2] + 2.f*w[3] - 2.f*w[4];
    o[2] = w[1] + w[2] + 4.f*w[3] + 4.f*w[4];
    o[3] = w[1] - w[2] + 8.f*w[3] - 8.f*w[4] + w[5];
}

__global__ __launch_bounds__(256) void k_wg_out(
    const float* __restrict__ cb, float* __restrict__ out)
{
    int tid = threadIdx.x;
    int tx = tid & 15, oc_l = tid >> 4;
    int ty = blockIdx.x, ocT = blockIdx.y, b = blockIdx.z;
    int oc = ocT*16 + oc_l;
    int tile = b*256 + ty*16 + tx;

    float m[6][6];
#pragma unroll
    for (int r = 0; r < 6; r++)
#pragma unroll
        for (int c = 0; c < 6; c++)
            m[r][c] = g_M[(size_t)(r*6+c)*CC*NTIL + (size_t)oc*NTIL + tile];

    float z[4][6];
#pragma unroll
    for (int j = 0; j < 6; j++) {
        float col[6] = {m[0][j], m[1][j], m[2][j], m[3][j], m[4][j], m[5][j]};
        float o[4];
        atrans(col, o);
#pragma unroll
        for (int i = 0; i < 4; i++) z[i][j] = o[i];
    }

    float bias = cb[oc];
    size_t chan = (size_t)b*CC + oc;
    const unsigned char* idxp  = g_idx  + chan*TT;
    const float*         projp = g_proj + chan*TT;
    float* op = out + chan*PP;

#pragma unroll
    for (int r = 0; r < 4; r++) {
        float y[4];
        atrans(z[r], y);
        int gy = ty*4 + r;
        int h2 = gy >> 1;
        int subr = (gy & 1) << 1;
        float v[4];
#pragma unroll
        for (int c = 0; c < 4; c++) {
            int gx = tx*4 + c;
            float vv = y[c] + bias;
            int w2 = gx >> 1;
            if (idxp[h2*32 + w2] == (unsigned char)(subr | (gx & 1)))
                vv += projp[h2*32 + w2];
            v[c] = vv;
        }
        *(float4*)(op + (size_t)gy*64 + tx*4) = make_float4(v[0], v[1], v[2], v[3]);
    }
}

// =====================================================================
extern "C" void kernel_launch(void* const* d_in, const int* in_sizes, int n_in,
                              void* d_out, int out_size)
{
    const float* x      = (const float*)d_in[0];
    const float* conv_w = (const float*)d_in[1];
    const float* conv_b = (const float*)d_in[2];
    const float* fr_w   = (const float*)d_in[3];
    const float* fr_b   = (const float*)d_in[4];
    const float* wq     = (const float*)d_in[5];
    const float* wk     = (const float*)d_in[6];
    const float* wv     = (const float*)d_in[7];
    const float* wo     = (const float*)d_in[8];
    const float* gamma  = (const float*)d_in[9];
    float* out = (float*)d_out;

    static cudaStream_t s1 = [](){
        cudaStream_t s; cudaStreamCreateWithFlags(&s, cudaStreamNonBlocking); return s; }();
    static cudaStream_t s2 = [](){
        cudaStream_t s; cudaStreamCreateWithFlags(&s, cudaStreamNonBlocking); return s; }();
    static cudaEvent_t ev_fork = [](){
        cudaEvent_t e; cudaEventCreateWithFlags(&e, cudaEventDisableTiming); return e; }();
    static cudaEvent_t ev_in = [](){
        cudaEvent_t e; cudaEventCreateWithFlags(&e, cudaEventDisableTiming); return e; }();
    static cudaEvent_t ev_j1 = [](){
        cudaEvent_t e; cudaEventCreateWithFlags(&e, cudaEventDisableTiming); return e; }();
    static cudaEvent_t ev_j2 = [](){
        cudaEvent_t e; cudaEventCreateWithFlags(&e, cudaEventDisableTiming); return e; }();
    static bool attr_ok = [](){
        cudaFuncSetAttribute(k_wg_gemm_tc,
                             cudaFuncAttributeMaxDynamicSharedMemorySize, 51200);
        return true; }();
    (void)attr_ok;

    cudaEventRecord(ev_fork, 0);
    cudaStreamWaitEvent(s1, ev_fork, 0);

    // s1: Winograd transform chain + fp32 GEMM half (fma pipe)
    k_wg_wt   <<<256, 256, 0, s1>>>(conv_w);
    k_wg_in   <<<dim3(16, 16, BB), 256, 0, s1>>>(x);
    cudaEventRecord(ev_in, s1);
    k_wg_gemm <<<dim3(64, 4, 36 - PSPLIT), 256, 0, s1>>>();
    cudaEventRecord(ev_j1, s1);

    // s2: 3xTF32 GEMM half (tensor pipe), waits for g_V
    cudaStreamWaitEvent(s2, ev_in, 0);
    k_wg_gemm_tc <<<dim3(32, 4, PSPLIT), 256, 51200, s2>>>();
    cudaEventRecord(ev_j2, s2);

    // default: attention chain (tensor pipe + fr_pool fma)
    k_fr_pool  <<<dim3(32, 4, BB),        256>>>(x, fr_w, fr_b);
    k_qkv_mma  <<<dim3(8, 12, BB),        256>>>(wq, wk, wv);
    k_attn_mma <<<dim3(8, BB*NHEADS, 1),  128>>>();
    k_proj_mma <<<dim3(8, 4, BB),         256>>>(wo, gamma);

    cudaStreamWaitEvent(0, ev_j1, 0);
    cudaStreamWaitEvent(0, ev_j2, 0);
    k_wg_out  <<<dim3(16, 16, BB), 256>>>(conv_b, out);
}

// round 17
// speedup vs baseline: 1.0130x; 1.0130x over previous
#include <cuda_runtime.h>
#include <math.h>
#include <stdint.h>

#define BB     16
#define CC     256
#define HH     64
#define WWID   64
#define PP     4096   // HH*WWID
#define TT     1024   // 32*32 pooled tokens
#define NHEADS 8
#define DHEAD  32
#define NTIL   4096   // 16 b * 256 tiles (16x16 tiles of 4x4 outputs)

// ---------------- scratch (device globals; no allocs allowed) ----------------
__device__ float         g_pooled[BB*CC*TT];           // [b][c][t]
__device__ unsigned char g_idx   [BB*CC*TT];           // argmax 0..3
__device__ float         g_q   [BB*NHEADS*DHEAD*TT];   // [bh][dhi][t]
__device__ float         g_k   [BB*NHEADS*DHEAD*TT];
__device__ float         g_v   [BB*NHEADS*DHEAD*TT];
__device__ float         g_attn[BB*NHEADS*DHEAD*TT];   // [bh][dhi][t]
__device__ float         g_proj[BB*CC*TT];             // [b][c][t], pre-scaled by tanh(gamma)
__device__ float         g_frwT[CC*CC];                // fr weights transposed [ic][oc]
__device__ float         g_U[36*CC*CC];                // [p][ic][oc]
__device__ float         g_V[36*CC*NTIL];              // [p][ic][tile]
__device__ float         g_M[36*CC*NTIL];              // [p][oc][tile]

// ---------------- tf32 mma helpers (fragment mapping validated R13/R14) -----
__device__ __forceinline__ float f2tf(float v) {
    uint32_t u;
    asm("cvt.rna.tf32.f32 %0, %1;" : "=r"(u) : "f"(v));
    return __uint_as_float(u);
}
__device__ __forceinline__ void split2(float v, float& hi, float& lo) {
    hi = f2tf(v);
    lo = f2tf(v - hi);
}
__device__ __forceinline__ void mma_tf32(float4& c, const uint32_t* a, uint2 b) {
    asm volatile(
        "mma.sync.aligned.m16n8k8.row.col.f32.tf32.tf32.f32 "
        "{%0,%1,%2,%3}, {%4,%5,%6,%7}, {%8,%9}, {%0,%1,%2,%3};"
        : "+f"(c.x), "+f"(c.y), "+f"(c.z), "+f"(c.w)
        : "r"(a[0]), "r"(a[1]), "r"(a[2]), "r"(a[3]), "r"(b.x), "r"(b.y));
}

// =====================================================================
// Kernel 0a: transpose fr weights [oc][ic] -> g_frwT [ic][oc]
// =====================================================================
__global__ __launch_bounds__(256) void k_frw_t(const float* __restrict__ frw)
{
    int idx = blockIdx.x*256 + threadIdx.x;   // 0..65535
    int ic = idx >> 8, oc = idx & 255;
    g_frwT[(size_t)ic*CC + oc] = frw[(size_t)oc*CC + ic];
}

// =====================================================================
// Kernel 1: 1x1 conv + bias + 2x2 maxpool via 3xTF32 tensor mma.
// C[oc 64][px 128 = rows {2hp,2hp+1}] = frwT^T x; hi/lo split -> ~fp32
// accuracy (product err ~2^-21) so argmax matches fp32 reference.
// Dynamic smem 51200B (template validated in R16 at full tensor rate).
// Grid (32 row-pairs, 4 ocT, 16 b), 256 thr.
// =====================================================================
#define AH(st,ks,m,c) sA_h[(((st)*2 + (ks))*64 + (m))*8 + (c)]
#define AL(st,ks,m,c) sA_l[(((st)*2 + (ks))*64 + (m))*8 + (c)]
#define BH(st,k,n)    sB_h[((st)*16 + (k))*136 + (n)]
#define BL(st,k,n)    sB_l[((st)*16 + (k))*136 + (n)]

__global__ __launch_bounds__(256) void k_fr_pool_tc(
    const float* __restrict__ x, const float* __restrict__ frb)
{
    extern __shared__ float dsm[];
    float* sA_h = dsm;              // 2048 floats
    float* sA_l = dsm + 2048;       // 2048
    float* sB_h = dsm + 4096;       // 4352
    float* sB_l = dsm + 8448;       // 4352 -> 12800 floats = 51200 B

    int tid = threadIdx.x;
    int lane = tid & 31, w = tid >> 5;
    int r = lane >> 2, cq = lane & 3;
    int wm = w >> 2, wn = w & 3;
    int hp = blockIdx.x;            // row pair
    int oc0 = blockIdx.y * 64;
    int b = blockIdx.z;

    const float* xb = x + (size_t)b*CC*PP + hp*128;   // rows 2hp,2hp+1

    int a_kk = tid >> 4, a_m = (tid & 15) * 4;
    int a_col = ((a_kk & 3) << 1) | ((a_kk >> 2) & 1);
    int a_ks  = a_kk >> 3;
    int b_kk0 = tid >> 5,       b_tq0 = (tid & 31) * 4;
    int b_kk1 = (tid >> 5) + 8, b_tq1 = b_tq0;

    float4 acc[2][4];
#pragma unroll
    for (int mt = 0; mt < 2; mt++)
#pragma unroll
        for (int nt = 0; nt < 4; nt++) acc[mt][nt] = make_float4(0.f,0.f,0.f,0.f);

    float4 ra, rb0, rb1;

    #define STAGE_FR(st) do {                                                  \
        float h, l;                                                            \
        split2(ra.x, h, l); AH(st,a_ks,a_m+0,a_col) = h; AL(st,a_ks,a_m+0,a_col) = l; \
        split2(ra.y, h, l); AH(st,a_ks,a_m+1,a_col) = h; AL(st,a_ks,a_m+1,a_col) = l; \
        split2(ra.z, h, l); AH(st,a_ks,a_m+2,a_col) = h; AL(st,a_ks,a_m+2,a_col) = l; \
        split2(ra.w, h, l); AH(st,a_ks,a_m+3,a_col) = h; AL(st,a_ks,a_m+3,a_col) = l; \
        float4 hv, lv;                                                         \
        split2(rb0.x, hv.x, lv.x); split2(rb0.y, hv.y, lv.y);                  \
        split2(rb0.z, hv.z, lv.z); split2(rb0.w, hv.w, lv.w);                  \
        *(float4*)&BH(st,b_kk0,b_tq0) = hv; *(float4*)&BL(st,b_kk0,b_tq0) = lv; \
        split2(rb1.x, hv.x, lv.x); split2(rb1.y, hv.y, lv.y);                  \
        split2(rb1.z, hv.z, lv.z); split2(rb1.w, hv.w, lv.w);                  \
        *(float4*)&BH(st,b_kk1,b_tq1) = hv; *(float4*)&BL(st,b_kk1,b_tq1) = lv; \
    } while (0)

    ra  = *(const float4*)(g_frwT + (size_t)a_kk*CC + oc0 + a_m);
    rb0 = *(const float4*)(xb + (size_t)b_kk0*PP + b_tq0);
    rb1 = *(const float4*)(xb + (size_t)b_kk1*PP + b_tq1);
    STAGE_FR(0);
    __syncthreads();
    ra  = *(const float4*)(g_frwT + (size_t)(16 + a_kk)*CC + oc0 + a_m);
    rb0 = *(const float4*)(xb + (size_t)(16 + b_kk0)*PP + b_tq0);
    rb1 = *(const float4*)(xb + (size_t)(16 + b_kk1)*PP + b_tq1);

    for (int s = 0; s < 16; s++) {
        int cur = s & 1;
#pragma unroll
        for (int ks = 0; ks < 2; ks++) {
            uint32_t ah[2][4], al[2][4];
#pragma unroll
            for (int mt = 0; mt < 2; mt++) {
                int mb = wm*32 + mt*16;
                float2 h0 = *(const float2*)&AH(cur,ks,mb + r,cq*2);
                float2 h1 = *(const float2*)&AH(cur,ks,mb + r + 8,cq*2);
                ah[mt][0] = __float_as_uint(h0.x); ah[mt][1] = __float_as_uint(h1.x);
                ah[mt][2] = __float_as_uint(h0.y); ah[mt][3] = __float_as_uint(h1.y);
                float2 l0 = *(const float2*)&AL(cur,ks,mb + r,cq*2);
                float2 l1 = *(const float2*)&AL(cur,ks,mb + r + 8,cq*2);
                al[mt][0] = __float_as_uint(l0.x); al[mt][1] = __float_as_uint(l1.x);
                al[mt][2] = __float_as_uint(l0.y); al[mt][3] = __float_as_uint(l1.y);
            }
#pragma unroll
            for (int nt = 0; nt < 4; nt++) {
                int nb = wn*32 + nt*8 + r;
                uint2 bh, bl;
                bh.x = __float_as_uint(BH(cur,ks*8 + cq,nb));
                bh.y = __float_as_uint(BH(cur,ks*8 + cq + 4,nb));
                bl.x = __float_as_uint(BL(cur,ks*8 + cq,nb));
                bl.y = __float_as_uint(BL(cur,ks*8 + cq + 4,nb));
#pragma unroll
                for (int mt = 0; mt < 2; mt++) {
                    mma_tf32(acc[mt][nt], ah[mt], bh);   // hi*hi
                    mma_tf32(acc[mt][nt], ah[mt], bl);   // hi*lo
                    mma_tf32(acc[mt][nt], al[mt], bh);   // lo*hi
                }
            }
        }
        if (s < 15) {
            __syncthreads();
            int nxt = cur ^ 1;
            STAGE_FR(nxt);
            if (s < 14) {
                int k0 = (s + 2) * 16;
                ra  = *(const float4*)(g_frwT + (size_t)(k0 + a_kk)*CC + oc0 + a_m);
                rb0 = *(const float4*)(xb + (size_t)(k0 + b_kk0)*PP + b_tq0);
                rb1 = *(const float4*)(xb + (size_t)(k0 + b_kk1)*PP + b_tq1);
            }
            __syncthreads();
        }
    }
    #undef STAGE_FR

    // ---- epilogue: frags -> smem [64 oc][132], then pool 2x2 + argmax
    __syncthreads();
    float* Cs = dsm;                // 64*132 = 8448 floats (fits 12800)
#pragma unroll
    for (int mt = 0; mt < 2; mt++) {
        int m = wm*32 + mt*16;
#pragma unroll
        for (int nt = 0; nt < 4; nt++) {
            float4 c = acc[mt][nt];
            int n = wn*32 + nt*8 + cq*2;
            *(float2*)&Cs[(m + r)*132 + n]     = make_float2(c.x, c.y);
            *(float2*)&Cs[(m + r + 8)*132 + n] = make_float2(c.z, c.w);
        }
    }
    __syncthreads();

#pragma unroll
    for (int j = 0; j < 8; j++) {
        int idx = tid + j*256;           // 0..2047
        int oc_l = idx >> 5, w2 = idx & 31;
        int oc = oc0 + oc_l;
        float bi = frb[oc];
        const float* row = Cs + oc_l*132;
        float a0 = row[w2*2] + bi,      a1 = row[w2*2 + 1] + bi;
        float a2 = row[64 + w2*2] + bi, a3 = row[64 + w2*2 + 1] + bi;
        float best = a0; int am = 0;
        if (a1 > best) { best = a1; am = 1; }
        if (a2 > best) { best = a2; am = 2; }
        if (a3 > best) { best = a3; am = 3; }
        size_t base = ((size_t)b*CC + oc)*TT + hp*32 + w2;
        g_pooled[base] = best;
        g_idx[base] = (unsigned char)am;
    }
}

// =====================================================================
// Kernel 2: QKV projection via mma.sync tf32 (unchanged from R14)
// =====================================================================
__global__ __launch_bounds__(256, 2) void k_qkv_mma(
    const float* __restrict__ wq, const float* __restrict__ wk,
    const float* __restrict__ wv)
{
    __shared__ float As[2][2][64][8];
    __shared__ float Bs[2][16][136];
    int tid = threadIdx.x;
    int lane = tid & 31, w = tid >> 5;
    int r = lane >> 2, cq = lane & 3;
    int wm = w >> 2, wn = w & 3;
    int t0 = blockIdx.x * 128;
    int mat = blockIdx.y >> 2, dT = blockIdx.y & 3;
    int b = blockIdx.z;
    int m0 = dT * 64;

    const float* W  = (mat == 0) ? wq : (mat == 1) ? wk : wv;
    const float* Bg = g_pooled + (size_t)b*CC*TT;

    int a_kk = tid >> 4, a_m = (tid & 15) * 4;
    int a_col = ((a_kk & 3) << 1) | ((a_kk >> 2) & 1);
    int a_ks  = a_kk >> 3;
    int b_kk0 = tid >> 5,        b_tq0 = (tid & 31) * 4;
    int b_kk1 = (tid >> 5) + 8,  b_tq1 = b_tq0;

    float4 acc[2][4];
#pragma unroll
    for (int mt = 0; mt < 2; mt++)
#pragma unroll
        for (int nt = 0; nt < 4; nt++) acc[mt][nt] = make_float4(0.f,0.f,0.f,0.f);

    float4 ra, rb0, rb1;
    ra  = *(const float4*)(W  + (size_t)a_kk*CC + m0 + a_m);
    rb0 = *(const float4*)(Bg + (size_t)b_kk0*TT + t0 + b_tq0);
    rb1 = *(const float4*)(Bg + (size_t)b_kk1*TT + t0 + b_tq1);
    As[0][a_ks][a_m+0][a_col] = f2tf(ra.x);
    As[0][a_ks][a_m+1][a_col] = f2tf(ra.y);
    As[0][a_ks][a_m+2][a_col] = f2tf(ra.z);
    As[0][a_ks][a_m+3][a_col] = f2tf(ra.w);
    *(float4*)&Bs[0][b_kk0][b_tq0] = make_float4(f2tf(rb0.x), f2tf(rb0.y), f2tf(rb0.z), f2tf(rb0.w));
    *(float4*)&Bs[0][b_kk1][b_tq1] = make_float4(f2tf(rb1.x), f2tf(rb1.y), f2tf(rb1.z), f2tf(rb1.w));
    __syncthreads();
    ra  = *(const float4*)(W  + (size_t)(16 + a_kk)*CC + m0 + a_m);
    rb0 = *(const float4*)(Bg + (size_t)(16 + b_kk0)*TT + t0 + b_tq0);
    rb1 = *(const float4*)(Bg + (size_t)(16 + b_kk1)*TT + t0 + b_tq1);

    for (int s = 0; s < 16; s++) {
        int cur = s & 1;
#pragma unroll
        for (int ks = 0; ks < 2; ks++) {
            uint32_t a[2][4];
#pragma unroll
            for (int mt = 0; mt < 2; mt++) {
                int mb = wm*32 + mt*16;
                float2 lo = *(const float2*)&As[cur][ks][mb + r][cq*2];
                float2 hi = *(const float2*)&As[cur][ks][mb + r + 8][cq*2];
                a[mt][0] = __float_as_uint(lo.x); a[mt][1] = __float_as_uint(hi.x);
                a[mt][2] = __float_as_uint(lo.y); a[mt][3] = __float_as_uint(hi.y);
            }
#pragma unroll
            for (int nt = 0; nt < 4; nt++) {
                int nb = wn*32 + nt*8 + r;
                uint2 bf;
                bf.x = __float_as_uint(Bs[cur][ks*8 + cq][nb]);
                bf.y = __float_as_uint(Bs[cur][ks*8 + cq + 4][nb]);
                mma_tf32(acc[0][nt], a[0], bf);
                mma_tf32(acc[1][nt], a[1], bf);
            }
        }
        if (s < 15) {
            __syncthreads();
            int nxt = cur ^ 1;
            As[nxt][a_ks][a_m+0][a_col] = f2tf(ra.x);
            As[nxt][a_ks][a_m+1][a_col] = f2tf(ra.y);
            As[nxt][a_ks][a_m+2][a_col] = f2tf(ra.z);
            As[nxt][a_ks][a_m+3][a_col] = f2tf(ra.w);
            *(float4*)&Bs[nxt][b_kk0][b_tq0] = make_float4(f2tf(rb0.x), f2tf(rb0.y), f2tf(rb0.z), f2tf(rb0.w));
            *(float4*)&Bs[nxt][b_kk1][b_tq1] = make_float4(f2tf(rb1.x), f2tf(rb1.y), f2tf(rb1.z), f2tf(rb1.w));
            if (s < 14) {
                int k0 = (s + 2) * 16;
                ra  = *(const float4*)(W  + (size_t)(k0 + a_kk)*CC + m0 + a_m);
                rb0 = *(const float4*)(Bg + (size_t)(k0 + b_kk0)*TT + t0 + b_tq0);
                rb1 = *(const float4*)(Bg + (size_t)(k0 + b_kk1)*TT + t0 + b_tq1);
            }
            __syncthreads();
        }
    }

    float* O = (mat == 0) ? g_q : (mat == 1) ? g_k : g_v;
#pragma unroll
    for (int mt = 0; mt < 2; mt++) {
        int dbase = m0 + wm*32 + mt*16;
#pragma unroll
        for (int nt = 0; nt < 4; nt++) {
            float4 c = acc[mt][nt];
            int t  = t0 + wn*32 + nt*8 + cq*2;
            int d1 = dbase + r, d2 = dbase + r + 8;
            size_t a1 = (((size_t)b*NHEADS + (d1 & 7))*DHEAD + (d1 >> 3))*TT + t;
            size_t a2 = (((size_t)b*NHEADS + (d2 & 7))*DHEAD + (d2 >> 3))*TT + t;
            *(float2*)&O[a1] = make_float2(c.x, c.y);
            *(float2*)&O[a2] = make_float2(c.z, c.w);
        }
    }
}

// =====================================================================
// Kernel 3: flash attention via mma.sync tf32 (unchanged from R14)
// =====================================================================
__global__ __launch_bounds__(128) void k_attn_mma()
{
    __shared__ float Qs[128][36];
    __shared__ float Ks[32][40];
    __shared__ float Vs[32][40];
    __shared__ float Ps[4][32][36];

    int tid = threadIdx.x;
    int lane = tid & 31, w = tid >> 5;
    int r = lane >> 2, cq = lane & 3;
    int q0 = blockIdx.x * 128;
    int bh = blockIdx.y;
    const float* Qg = g_q + (size_t)bh*DHEAD*TT;
    const float* Kg = g_k + (size_t)bh*DHEAD*TT;
    const float* Vg = g_v + (size_t)bh*DHEAD*TT;
    const float qscale = 0.17677669529663687f;

#pragma unroll
    for (int j = 0; j < 8; j++) {
        int e = tid + j*128;
        int d = e >> 5, q4 = (e & 31) * 4;
        float4 v = *(const float4*)(Qg + (size_t)d*TT + q0 + q4);
        Qs[q4+0][d] = f2tf(v.x * qscale);
        Qs[q4+1][d] = f2tf(v.y * qscale);
        Qs[q4+2][d] = f2tf(v.z * qscale);
        Qs[q4+3][d] = f2tf(v.w * qscale);
    }

    float mrow[2][2], lrow[2][2];
#pragma unroll
    for (int mt = 0; mt < 2; mt++) {
        mrow[mt][0] = -3.0e38f; mrow[mt][1] = -3.0e38f;
        lrow[mt][0] = 0.f;      lrow[mt][1] = 0.f;
    }
    float4 of[2][4];
#pragma unroll
    for (int mt = 0; mt < 2; mt++)
#pragma unroll
        for (int nt = 0; nt < 4; nt++) of[mt][nt] = make_float4(0.f,0.f,0.f,0.f);

    for (int k0 = 0; k0 < TT; k0 += 32) {
#pragma unroll
        for (int j = 0; j < 2; j++) {
            int e = tid + j*128;
            int d = e >> 3, c4 = (e & 7) * 4;
            float4 kv = *(const float4*)(Kg + (size_t)d*TT + k0 + c4);
            Ks[d][c4+0] = f2tf(kv.x); Ks[d][c4+1] = f2tf(kv.y);
            Ks[d][c4+2] = f2tf(kv.z); Ks[d][c4+3] = f2tf(kv.w);
            float4 vv = *(const float4*)(Vg + (size_t)d*TT + k0 + c4);
            Vs[c4+0][d] = f2tf(vv.x); Vs[c4+1][d] = f2tf(vv.y);
            Vs[c4+2][d] = f2tf(vv.z); Vs[c4+3][d] = f2tf(vv.w);
        }
        __syncthreads();

        float4 s[2][4];
#pragma unroll
        for (int mt = 0; mt < 2; mt++)
#pragma unroll
            for (int nt = 0; nt < 4; nt++) s[mt][nt] = make_float4(0.f,0.f,0.f,0.f);
#pragma unroll
        for (int ks = 0; ks < 4; ks++) {
            uint32_t a[2][4];
#pragma unroll
            for (int mt = 0; mt < 2; mt++) {
                int mb = w*32 + mt*16;
                a[mt][0] = __float_as_uint(Qs[mb + r    ][ks*8 + cq]);
                a[mt][1] = __float_as_uint(Qs[mb + r + 8][ks*8 + cq]);
                a[mt][2] = __float_as_uint(Qs[mb + r    ][ks*8 + cq + 4]);
                a[mt][3] = __float_as_uint(Qs[mb + r + 8][ks*8 + cq + 4]);
            }
#pragma unroll
            for (int nt = 0; nt < 4; nt++) {
                uint2 bf;
                bf.x = __float_as_uint(Ks[ks*8 + cq    ][nt*8 + r]);
                bf.y = __float_as_uint(Ks[ks*8 + cq + 4][nt*8 + r]);
                mma_tf32(s[0][nt], a[0], bf);
                mma_tf32(s[1][nt], a[1], bf);
            }
        }

#pragma unroll
        for (int mt = 0; mt < 2; mt++) {
            float vm0 = -3.0e38f, vm1 = -3.0e38f;
#pragma unroll
            for (int nt = 0; nt < 4; nt++) {
                vm0 = fmaxf(vm0, fmaxf(s[mt][nt].x, s[mt][nt].y));
                vm1 = fmaxf(vm1, fmaxf(s[mt][nt].z, s[mt][nt].w));
            }
            vm0 = fmaxf(vm0, __shfl_xor_sync(0xffffffffu, vm0, 1));
            vm0 = fmaxf(vm0, __shfl_xor_sync(0xffffffffu, vm0, 2));
            vm1 = fmaxf(vm1, __shfl_xor_sync(0xffffffffu, vm1, 1));
            vm1 = fmaxf(vm1, __shfl_xor_sync(0xffffffffu, vm1, 2));
            float mn0 = fmaxf(mrow[mt][0], vm0);
            float mn1 = fmaxf(mrow[mt][1], vm1);
            float al0 = __expf(mrow[mt][0] - mn0);
            float al1 = __expf(mrow[mt][1] - mn1);
            float sum0 = 0.f, sum1 = 0.f;
            int rowa = mt*16 + r, rowb = rowa + 8;
#pragma unroll
            for (int nt = 0; nt < 4; nt++) {
                float p00 = __expf(s[mt][nt].x - mn0);
                float p01 = __expf(s[mt][nt].y - mn0);
                float p10 = __expf(s[mt][nt].z - mn1);
                float p11 = __expf(s[mt][nt].w - mn1);
                Ps[w][rowa][nt*8 + cq*2]     = f2tf(p00);
                Ps[w][rowa][nt*8 + cq*2 + 1] = f2tf(p01);
                Ps[w][rowb][nt*8 + cq*2]     = f2tf(p10);
                Ps[w][rowb][nt*8 + cq*2 + 1] = f2tf(p11);
                sum0 += p00 + p01;
                sum1 += p10 + p11;
            }
            sum0 += __shfl_xor_sync(0xffffffffu, sum0, 1);
            sum0 += __shfl_xor_sync(0xffffffffu, sum0, 2);
            sum1 += __shfl_xor_sync(0xffffffffu, sum1, 1);
            sum1 += __shfl_xor_sync(0xffffffffu, sum1, 2);
            lrow[mt][0] = lrow[mt][0]*al0 + sum0;  mrow[mt][0] = mn0;
            lrow[mt][1] = lrow[mt][1]*al1 + sum1;  mrow[mt][1] = mn1;
#pragma unroll
            for (int nt = 0; nt < 4; nt++) {
                of[mt][nt].x *= al0; of[mt][nt].y *= al0;
                of[mt][nt].z *= al1; of[mt][nt].w *= al1;
            }
        }
        __syncwarp();

#pragma unroll
        for (int ks = 0; ks < 4; ks++) {
            uint32_t a[2][4];
#pragma unroll
            for (int mt = 0; mt < 2; mt++) {
                int mb = mt*16;
                a[mt][0] = __float_as_uint(Ps[w][mb + r    ][ks*8 + cq]);
                a[mt][1] = __float_as_uint(Ps[w][mb + r + 8][ks*8 + cq]);
                a[mt][2] = __float_as_uint(Ps[w][mb + r    ][ks*8 + cq + 4]);
                a[mt][3] = __float_as_uint(Ps[w][mb + r + 8][ks*8 + cq + 4]);
            }
#pragma unroll
            for (int nt = 0; nt < 4; nt++) {
                uint2 bf;
                bf.x = __float_as_uint(Vs[ks*8 + cq    ][nt*8 + r]);
                bf.y = __float_as_uint(Vs[ks*8 + cq + 4][nt*8 + r]);
                mma_tf32(of[0][nt], a[0], bf);
                mma_tf32(of[1][nt], a[1], bf);
            }
        }
        __syncthreads();
    }

    float* Og = g_attn + (size_t)bh*DHEAD*TT;
#pragma unroll
    for (int mt = 0; mt < 2; mt++) {
        float li0 = 1.f / lrow[mt][0];
        float li1 = 1.f / lrow[mt][1];
        int qr = q0 + w*32 + mt*16 + r;
#pragma unroll
        for (int nt = 0; nt < 4; nt++) {
            float4 c = of[mt][nt];
            int d0 = nt*8 + cq*2;
            Og[(size_t)d0*TT + qr]           = c.x * li0;
            Og[(size_t)(d0+1)*TT + qr]       = c.y * li0;
            Og[(size_t)d0*TT + qr + 8]       = c.z * li1;
            Og[(size_t)(d0+1)*TT + qr + 8]   = c.w * li1;
        }
    }
}

// =====================================================================
// Kernel 4: output projection via mma.sync tf32 (unchanged from R14)
// =====================================================================
__global__ __launch_bounds__(256, 2) void k_proj_mma(
    const float* __restrict__ wo, const float* __restrict__ gamma)
{
    __shared__ float As[2][2][64][8];
    __shared__ float Bs[2][16][136];
    int tid = threadIdx.x;
    int lane = tid & 31, w = tid >> 5;
    int r = lane >> 2, cq = lane & 3;
    int wm = w >> 2, wn = w & 3;
    int t0 = blockIdx.x * 128;
    int dT = blockIdx.y;
    int b = blockIdx.z;
    int m0 = dT * 64;

    int a_kk = tid >> 4, a_m = (tid & 15) * 4;
    int a_col = ((a_kk & 3) << 1) | ((a_kk >> 2) & 1);
    int a_ks  = a_kk >> 3;
    int b_kk0 = tid >> 5,       b_tq0 = (tid & 31) * 4;
    int b_kk1 = (tid >> 5) + 8, b_tq1 = b_tq0;

    #define ATTN_ROW(c) (g_attn + (((size_t)b*NHEADS + ((c) & 7))*DHEAD + ((c) >> 3))*TT)

    float4 acc[2][4];
#pragma unroll
    for (int mt = 0; mt < 2; mt++)
#pragma unroll
        for (int nt = 0; nt < 4; nt++) acc[mt][nt] = make_float4(0.f,0.f,0.f,0.f);

    float4 ra, rb0, rb1;
    ra  = *(const float4*)(wo + (size_t)a_kk*CC + m0 + a_m);
    rb0 = *(const float4*)(ATTN_ROW(b_kk0) + t0 + b_tq0);
    rb1 = *(const float4*)(ATTN_ROW(b_kk1) + t0 + b_tq1);
    As[0][a_ks][a_m+0][a_col] = f2tf(ra.x);
    As[0][a_ks][a_m+1][a_col] = f2tf(ra.y);
    As[0][a_ks][a_m+2][a_col] = f2tf(ra.z);
    As[0][a_ks][a_m+3][a_col] = f2tf(ra.w);
    *(float4*)&Bs[0][b_kk0][b_tq0] = make_float4(f2tf(rb0.x), f2tf(rb0.y), f2tf(rb0.z), f2tf(rb0.w));
    *(float4*)&Bs[0][b_kk1][b_tq1] = make_float4(f2tf(rb1.x), f2tf(rb1.y), f2tf(rb1.z), f2tf(rb1.w));
    __syncthreads();
    ra  = *(const float4*)(wo + (size_t)(16 + a_kk)*CC + m0 + a_m);
    rb0 = *(const float4*)(ATTN_ROW(16 + b_kk0) + t0 + b_tq0);
    rb1 = *(const float4*)(ATTN_ROW(16 + b_kk1) + t0 + b_tq1);

    for (int s = 0; s < 16; s++) {
        int cur = s & 1;
#pragma unroll
        for (int ks = 0; ks < 2; ks++) {
            uint32_t a[2][4];
#pragma unroll
            for (int mt = 0; mt < 2; mt++) {
                int mb = wm*32 + mt*16;
                float2 lo = *(const float2*)&As[cur][ks][mb + r][cq*2];
                float2 hi = *(const float2*)&As[cur][ks][mb + r + 8][cq*2];
                a[mt][0] = __float_as_uint(lo.x); a[mt][1] = __float_as_uint(hi.x);
                a[mt][2] = __float_as_uint(lo.y); a[mt][3] = __float_as_uint(hi.y);
            }
#pragma unroll
            for (int nt = 0; nt < 4; nt++) {
                int nb = wn*32 + nt*8 + r;
                uint2 bf;
                bf.x = __float_as_uint(Bs[cur][ks*8 + cq][nb]);
                bf.y = __float_as_uint(Bs[cur][ks*8 + cq + 4][nb]);
                mma_tf32(acc[0][nt], a[0], bf);
                mma_tf32(acc[1][nt], a[1], bf);
            }
        }
        if (s < 15) {
            __syncthreads();
            int nxt = cur ^ 1;
            As[nxt][a_ks][a_m+0][a_col] = f2tf(ra.x);
            As[nxt][a_ks][a_m+1][a_col] = f2tf(ra.y);
            As[nxt][a_ks][a_m+2][a_col] = f2tf(ra.z);
            As[nxt][a_ks][a_m+3][a_col] = f2tf(ra.w);
            *(float4*)&Bs[nxt][b_kk0][b_tq0] = make_float4(f2tf(rb0.x), f2tf(rb0.y), f2tf(rb0.z), f2tf(rb0.w));
            *(float4*)&Bs[nxt][b_kk1][b_tq1] = make_float4(f2tf(rb1.x), f2tf(rb1.y), f2tf(rb1.z), f2tf(rb1.w));
            if (s < 14) {
                int k0 = (s + 2) * 16;
                ra  = *(const float4*)(wo + (size_t)(k0 + a_kk)*CC + m0 + a_m);
                rb0 = *(const float4*)(ATTN_ROW(k0 + b_kk0) + t0 + b_tq0);
                rb1 = *(const float4*)(ATTN_ROW(k0 + b_kk1) + t0 + b_tq1);
            }
            __syncthreads();
        }
    }
    #undef ATTN_ROW

    float tg = tanhf(gamma[0]);
#pragma unroll
    for (int mt = 0; mt < 2; mt++) {
        int dbase = m0 + wm*32 + mt*16;
#pragma unroll
        for (int nt = 0; nt < 4; nt++) {
            float4 c = acc[mt][nt];
            int t  = t0 + wn*32 + nt*8 + cq*2;
            size_t a1 = ((size_t)b*CC + dbase + r)*TT + t;
            size_t a2 = ((size_t)b*CC + dbase + r + 8)*TT + t;
            *(float2*)&g_proj[a1] = make_float2(c.x*tg, c.y*tg);
            *(float2*)&g_proj[a2] = make_float2(c.z*tg, c.w*tg);
        }
    }
}

// =====================================================================
// Winograd F(4x4, 3x3)  (fp32 on fma pipe; all 36 positions)
// =====================================================================
__device__ __forceinline__ void gfilt(const float a, const float b, const float c,
                                      float* o) {
    o[0] = 0.25f*a;
    o[1] = (-a - b - c) * (1.f/6.f);
    o[2] = (-a + b - c) * (1.f/6.f);
    o[3] = a*(1.f/24.f) + b*(1.f/12.f) + c*(1.f/6.f);
    o[4] = a*(1.f/24.f) - b*(1.f/12.f) + c*(1.f/6.f);
    o[5] = c;
}

__global__ __launch_bounds__(256) void k_wg_wt(const float* __restrict__ cw)
{
    int idx = blockIdx.x*256 + threadIdx.x;
    int oc = idx & 255, ic = idx >> 8;
    const float* g = cw + (size_t)oc*2304 + ic*9;
    float g00=g[0],g01=g[1],g02=g[2],g10=g[3],g11=g[4],g12=g[5],g20=g[6],g21=g[7],g22=g[8];

    float t[6][3];
    {
        float o0[6], o1[6], o2[6];
        gfilt(g00, g10, g20, o0);
        gfilt(g01, g11, g21, o1);
        gfilt(g02, g12, g22, o2);
#pragma unroll
        for (int r = 0; r < 6; r++) { t[r][0]=o0[r]; t[r][1]=o1[r]; t[r][2]=o2[r]; }
    }
#pragma unroll
    for (int r = 0; r < 6; r++) {
        float o[6];
        gfilt(t[r][0], t[r][1], t[r][2], o);
#pragma unroll
        for (int c = 0; c < 6; c++)
            g_U[(size_t)(r*6+c)*CC*CC + (size_t)ic*CC + oc] = o[c];
    }
}

__device__ __forceinline__ void btrans(const float* d, float* o) {
    o[0] = 4.f*d[0] - 5.f*d[2] + d[4];
    o[1] = -4.f*d[1] - 4.f*d[2] + d[3] + d[4];
    o[2] =  4.f*d[1] - 4.f*d[2] - d[3] + d[4];
    o[3] = -2.f*d[1] -     d[2] + 2.f*d[3] + d[4];
    o[4] =  2.f*d[1] -     d[2] - 2.f*d[3] + d[4];
    o[5] =  4.f*d[1] - 5.f*d[3] + d[5];
}

__global__ __launch_bounds__(256) void k_wg_in(const float* __restrict__ x)
{
    int tid = threadIdx.x;
    int tx = tid & 15, ic_l = tid >> 4;
    int ty = blockIdx.x, icT = blockIdx.y, b = blockIdx.z;
    int ic = icT*16 + ic_l;
    int tile = b*256 + ty*16 + tx;

    const float* xp = x + ((size_t)b*CC + ic)*PP;
    int gy0 = ty*4 - 1, gx0 = tx*4 - 1;

    float d[6][6];
#pragma unroll
    for (int i = 0; i < 6; i++) {
        int gy = gy0 + i;
        bool yok = (unsigned)gy < 64u;
#pragma unroll
        for (int j = 0; j < 6; j++) {
            int gx = gx0 + j;
            d[i][j] = (yok && (unsigned)gx < 64u) ? xp[gy*64 + gx] : 0.f;
        }
    }
    float wcol[6][6];
#pragma unroll
    for (int j = 0; j < 6; j++) {
        float col[6] = {d[0][j], d[1][j], d[2][j], d[3][j], d[4][j], d[5][j]};
        float o[6];
        btrans(col, o);
#pragma unroll
        for (int r = 0; r < 6; r++) wcol[r][j] = o[r];
    }
#pragma unroll
    for (int r = 0; r < 6; r++) {
        float o[6];
        btrans(wcol[r], o);
#pragma unroll
        for (int c = 0; c < 6; c++)
            g_V[(size_t)(r*6+c)*CC*NTIL + (size_t)ic*NTIL + tile] = o[c];
    }
}

__global__ __launch_bounds__(256) void k_wg_gemm()
{
    __shared__ float As[32][64];
    __shared__ float Bs[32][64];
    int tid = threadIdx.x;
    int t0 = blockIdx.x*64, oc0 = blockIdx.y*64, p = blockIdx.z;
    int ng = tid & 15, mg = tid >> 4;

    const float* Vp = g_V + (size_t)p*CC*NTIL;
    const float* Up = g_U + (size_t)p*CC*CC;

    float acc[4][4];
#pragma unroll
    for (int i = 0; i < 4; i++)
#pragma unroll
        for (int j = 0; j < 4; j++) acc[i][j] = 0.f;

    for (int c0 = 0; c0 < CC; c0 += 32) {
#pragma unroll
        for (int j = 0; j < 2; j++) {
            int f = tid + j*256;
            int k = f >> 4, m4 = f & 15;
            *(float4*)&As[k][m4*4] = *(const float4*)(Vp + (size_t)(c0+k)*NTIL + t0 + m4*4);
            *(float4*)&Bs[k][m4*4] = *(const float4*)(Up + (size_t)(c0+k)*CC + oc0 + m4*4);
        }
        __syncthreads();
#pragma unroll 8
        for (int k = 0; k < 32; k++) {
            float4 a  = *(const float4*)&As[k][mg*4];
            float4 bv = *(const float4*)&Bs[k][ng*4];
            float am[4] = {a.x,a.y,a.z,a.w};
            float bn[4] = {bv.x,bv.y,bv.z,bv.w};
#pragma unroll
            for (int mm = 0; mm < 4; mm++)
#pragma unroll
                for (int nn = 0; nn < 4; nn++)
                    acc[mm][nn] = fmaf(am[mm], bn[nn], acc[mm][nn]);
        }
        __syncthreads();
    }

    float* Mp = g_M + (size_t)p*CC*NTIL;
#pragma unroll
    for (int nn = 0; nn < 4; nn++) {
        int oc = oc0 + ng*4 + nn;
        *(float4*)(Mp + (size_t)oc*NTIL + t0 + mg*4) =
            make_float4(acc[0][nn], acc[1][nn], acc[2][nn], acc[3][nn]);
    }
}

__device__ __forceinline__ void atrans(const float* w, float* o) {
    o[0] = w[0] + w[1] + w[2] + w[3] + w[4];
    o[1] = w[1] - w[2] + 2.f*w[3] - 2.f*w[4];
    o[2] = w[1] + w[2] + 4.f*w[3] + 4.f*w[4];
    o[3] = w[1] - w[2] + 8.f*w[3] - 8.f*w[4] + w[5];
}

__global__ __launch_bounds__(256) void k_wg_out(
    const float* __restrict__ cb, float* __restrict__ out)
{
    int tid = threadIdx.x;
    int tx = tid & 15, oc_l = tid >> 4;
    int ty = blockIdx.x, ocT = blockIdx.y, b = blockIdx.z;
    int oc = ocT*16 + oc_l;
    int tile = b*256 + ty*16 + tx;

    float m[6][6];
#pragma unroll
    for (int r = 0; r < 6; r++)
#pragma unroll
        for (int c = 0; c < 6; c++)
            m[r][c] = g_M[(size_t)(r*6+c)*CC*NTIL + (size_t)oc*NTIL + tile];

    float z[4][6];
#pragma unroll
    for (int j = 0; j < 6; j++) {
        float col[6] = {m[0][j], m[1][j], m[2][j], m[3][j], m[4][j], m[5][j]};
        float o[4];
        atrans(col, o);
#pragma unroll
        for (int i = 0; i < 4; i++) z[i][j] = o[i];
    }

    float bias = cb[oc];
    size_t chan = (size_t)b*CC + oc;
    const unsigned char* idxp  = g_idx  + chan*TT;
    const float*         projp = g_proj + chan*TT;
    float* op = out + chan*PP;

#pragma unroll
    for (int r = 0; r < 4; r++) {
        float y[4];
        atrans(z[r], y);
        int gy = ty*4 + r;
        int h2 = gy >> 1;
        int subr = (gy & 1) << 1;
        float v[4];
#pragma unroll
        for (int c = 0; c < 4; c++) {
            int gx = tx*4 + c;
            float vv = y[c] + bias;
            int w2 = gx >> 1;
            if (idxp[h2*32 + w2] == (unsigned char)(subr | (gx & 1)))
                vv += projp[h2*32 + w2];
            v[c] = vv;
        }
        *(float4*)(op + (size_t)gy*64 + tx*4) = make_float4(v[0], v[1], v[2], v[3]);
    }
}

// =====================================================================
extern "C" void kernel_launch(void* const* d_in, const int* in_sizes, int n_in,
                              void* d_out, int out_size)
{
    const float* x      = (const float*)d_in[0];
    const float* conv_w = (const float*)d_in[1];
    const float* conv_b = (const float*)d_in[2];
    const float* fr_w   = (const float*)d_in[3];
    const float* fr_b   = (const float*)d_in[4];
    const float* wq     = (const float*)d_in[5];
    const float* wk     = (const float*)d_in[6];
    const float* wv     = (const float*)d_in[7];
    const float* wo     = (const float*)d_in[8];
    const float* gamma  = (const float*)d_in[9];
    float* out = (float*)d_out;

    static cudaStream_t s1 = [](){
        cudaStream_t s; cudaStreamCreateWithFlags(&s, cudaStreamNonBlocking); return s; }();
    static cudaEvent_t ev_fork = [](){
        cudaEvent_t e; cudaEventCreateWithFlags(&e, cudaEventDisableTiming); return e; }();
    static cudaEvent_t ev_join = [](){
        cudaEvent_t e; cudaEventCreateWithFlags(&e, cudaEventDisableTiming); return e; }();
    static bool attr_ok = [](){
        cudaFuncSetAttribute(k_fr_pool_tc,
                             cudaFuncAttributeMaxDynamicSharedMemorySize, 51200);
        return true; }();
    (void)attr_ok;

    cudaEventRecord(ev_fork, 0);
    cudaStreamWaitEvent(s1, ev_fork, 0);

    // s1: Winograd chain (fma pipe)
    k_wg_wt   <<<256, 256, 0, s1>>>(conv_w);
    k_wg_in   <<<dim3(16, 16, BB), 256, 0, s1>>>(x);
    k_wg_gemm <<<dim3(64, 4, 36),  256, 0, s1>>>();
    cudaEventRecord(ev_join, s1);

    // default: attention chain, all on tensor pipe now
    k_frw_t      <<<256, 256>>>(fr_w);
    k_fr_pool_tc <<<dim3(32, 4, BB),        256, 51200>>>(x, fr_b);
    k_qkv_mma    <<<dim3(8, 12, BB),        256>>>(wq, wk, wv);
    k_attn_mma   <<<dim3(8, BB*NHEADS, 1),  128>>>();
    k_proj_mma   <<<dim3(8, 4, BB),         256>>>(wo, gamma);

    cudaStreamWaitEvent(0, ev_join, 0);
    k_wg_out  <<<dim3(16, 16, BB), 256>>>(conv_b, out);
}